// round 7
// baseline (speedup 1.0000x reference)
#include <cuda_runtime.h>
#include <cuda_fp16.h>
#include <cstdint>
#include <utility>

#define NTOK 2048
#define IFEAT 256
#define OFEAT 256
#define MDIM 8192            // GEMM M = NTOK*4
#define NC   1024            // complex GEMM N
#define KC   1024            // complex GEMM K

#define BM 128
#define BN 128
#define BK 64                // 64 halfs = 128 B per smem row
#define STAGES 3
#define NIT (KC / BK)        // 16
#define STAGE_BYTES 32768    // A 16KB + B 16KB
#define SMEM_TOTAL (STAGES * STAGE_BYTES)

#define A_CHUNK ((size_t)MDIM * KC)   // halfs
#define B_CHUNK ((size_t)NC * KC)

// ---- scratch ----
__device__ __half g_A[3 * A_CHUNK];   // 48 MB: Xre, Xim, Xre+Xim  (fp16)
__device__ __half g_B[3 * B_CHUNK];   // 6 MB:  Wre, Wim, Wre+Wim

// ================= compile-time Cl(4,1) -> M4(C) representation =================
struct Rho { int col[32][4]; int code[32][4]; int s[32]; };

constexpr Rho make_rho() {
    Rho R{};
    int gc[5][4] = {}; int gv[5][4] = {};
    for (int r = 0; r < 4; r++) {
        int a = r >> 1, b = r & 1;
        gc[0][r] = r ^ 2; gv[0][r] = b ? 2 : 0;                              // s1 (x) E
        gc[1][r] = r ^ 2; gv[1][r] = ((a ? 1 : 3) + (b ? 2 : 0)) & 3;        // s2 (x) E
        gc[2][r] = r;     gv[2][r] = ((a ? 2 : 0) + (b ? 2 : 0)) & 3;        // s3 (x) E
        gc[3][r] = r ^ 1; gv[3][r] = 0;                                      // I (x) sx
        gc[4][r] = r ^ 1; gv[4][r] = b ? 2 : 0;                              // I (x) J
    }
    for (int A = 0; A < 32; A++) {
        int pc[4] = {0, 1, 2, 3}, pv[4] = {0, 0, 0, 0};
        for (int i = 0; i < 5; i++)
            if ((A >> i) & 1)
                for (int r = 0; r < 4; r++) {
                    int t = pc[r];
                    pc[r] = gc[i][t];
                    pv[r] = (pv[r] + gv[i][t]) & 3;
                }
        for (int r = 0; r < 4; r++) { R.col[A][r] = pc[r]; R.code[A][r] = pv[r]; }
        int sq = (pv[0] + pv[pc[0]]) & 3;
        R.s[A] = (sq == 0) ? 1 : -1;
    }
    return R;
}
constexpr Rho RHO = make_rho();

// ---- template-unrolled transforms ----
template<int A, int R>
__device__ __forceinline__ void fx1(const float* v, float (&Lre)[4][4], float (&Lim)[4][4]) {
    constexpr int c = RHO.col[A][R];
    constexpr int k = RHO.code[A][R];
    if constexpr (k == 0) Lre[c][R] += v[A];
    else if constexpr (k == 1) Lim[c][R] += v[A];
    else if constexpr (k == 2) Lre[c][R] -= v[A];
    else                       Lim[c][R] -= v[A];
}
template<int A>
__device__ __forceinline__ void fxA(const float* v, float (&Lre)[4][4], float (&Lim)[4][4]) {
    fx1<A,0>(v,Lre,Lim); fx1<A,1>(v,Lre,Lim); fx1<A,2>(v,Lre,Lim); fx1<A,3>(v,Lre,Lim);
}
template<int... As>
__device__ __forceinline__ void fxall(const float* v, float (&Lre)[4][4], float (&Lim)[4][4],
                                      std::integer_sequence<int, As...>) {
    (fxA<As>(v, Lre, Lim), ...);
}
template<int A, int R>
__device__ __forceinline__ void fw1(const float* v, float (&Wre)[4][4], float (&Wim)[4][4]) {
    constexpr int c = RHO.col[A][R];
    constexpr int k = RHO.code[A][R];
    if constexpr (k == 0) Wre[R][c] += v[A];
    else if constexpr (k == 1) Wim[R][c] += v[A];
    else if constexpr (k == 2) Wre[R][c] -= v[A];
    else                       Wim[R][c] -= v[A];
}
template<int A>
__device__ __forceinline__ void fwA(const float* v, float (&Wre)[4][4], float (&Wim)[4][4]) {
    fw1<A,0>(v,Wre,Wim); fw1<A,1>(v,Wre,Wim); fw1<A,2>(v,Wre,Wim); fw1<A,3>(v,Wre,Wim);
}
template<int... As>
__device__ __forceinline__ void fwall(const float* v, float (&Wre)[4][4], float (&Wim)[4][4],
                                      std::integer_sequence<int, As...>) {
    (fwA<As>(v, Wre, Wim), ...);
}
template<int A, int R>
__device__ __forceinline__ float iv1(const float (&Mre)[4][4], const float (&Mim)[4][4]) {
    constexpr int t = RHO.col[A][R];
    constexpr int k = RHO.code[A][R];
    if constexpr (k == 0) return  Mre[t][R];
    else if constexpr (k == 1) return -Mim[t][R];
    else if constexpr (k == 2) return -Mre[t][R];
    else                       return  Mim[t][R];
}
template<int A>
__device__ __forceinline__ float bladeA(const float (&Mre)[4][4], const float (&Mim)[4][4]) {
    constexpr float s = 0.25f * (float)RHO.s[A];
    return s * (iv1<A,0>(Mre,Mim) + iv1<A,1>(Mre,Mim) + iv1<A,2>(Mre,Mim) + iv1<A,3>(Mre,Mim));
}
template<int... As>
__device__ __forceinline__ void blades(float* v, const float (&Mre)[4][4], const float (&Mim)[4][4],
                                       std::integer_sequence<int, As...>) {
    ((v[As] = bladeA<As>(Mre, Mim)), ...);
}

// ================= PTX helpers =================
__device__ __forceinline__ uint32_t smem_u32(const void* p) {
    uint32_t a;
    asm("{ .reg .u64 t; cvta.to.shared.u64 t, %1; cvt.u32.u64 %0, t; }" : "=r"(a) : "l"(p));
    return a;
}
__device__ __forceinline__ void cp16(uint32_t s, const void* g) {
    asm volatile("cp.async.cg.shared.global [%0], [%1], 16;" :: "r"(s), "l"(g) : "memory");
}
__device__ __forceinline__ void ldsm4(uint32_t* r, uint32_t a) {
    asm volatile("ldmatrix.sync.aligned.m8n8.x4.shared.b16 {%0,%1,%2,%3}, [%4];"
        : "=r"(r[0]), "=r"(r[1]), "=r"(r[2]), "=r"(r[3]) : "r"(a));
}
__device__ __forceinline__ void mma16(float* d, const uint32_t* a, uint32_t b0, uint32_t b1) {
    asm volatile("mma.sync.aligned.m16n8k16.row.col.f32.f16.f16.f32 "
        "{%0,%1,%2,%3}, {%4,%5,%6,%7}, {%8,%9}, {%0,%1,%2,%3};"
        : "+f"(d[0]), "+f"(d[1]), "+f"(d[2]), "+f"(d[3])
        : "r"(a[0]), "r"(a[1]), "r"(a[2]), "r"(a[3]), "r"(b0), "r"(b1));
}
__device__ __forceinline__ uint2 h4(float a, float b, float c, float d) {
    __half2 lo = __floats2half2_rn(a, b);
    __half2 hi = __floats2half2_rn(c, d);
    uint2 r;
    r.x = *reinterpret_cast<uint32_t*>(&lo);
    r.y = *reinterpret_cast<uint32_t*>(&hi);
    return r;
}

// ================= transform kernels =================
__global__ __launch_bounds__(128) void fwd_x(const float* __restrict__ x) {
    int idx = blockIdx.x * 128 + threadIdx.x;         // (n,i), i fastest
    float v[32];
    const float4* xv = reinterpret_cast<const float4*>(x) + (size_t)idx * 8;
    #pragma unroll
    for (int q = 0; q < 8; q++) {
        float4 t = xv[q];
        v[4*q] = t.x; v[4*q+1] = t.y; v[4*q+2] = t.z; v[4*q+3] = t.w;
    }
    float Lre[4][4] = {}, Lim[4][4] = {};
    fxall(v, Lre, Lim, std::make_integer_sequence<int, 32>{});
    int n = idx >> 8, i = idx & 255;
    #pragma unroll
    for (int c = 0; c < 4; c++) {
        size_t base = (size_t)(n * 4 + c) * KC + i * 4;
        *reinterpret_cast<uint2*>(g_A + base) =
            h4(Lre[c][0], Lre[c][1], Lre[c][2], Lre[c][3]);
        *reinterpret_cast<uint2*>(g_A + A_CHUNK + base) =
            h4(Lim[c][0], Lim[c][1], Lim[c][2], Lim[c][3]);
        *reinterpret_cast<uint2*>(g_A + 2 * A_CHUNK + base) =
            h4(Lre[c][0] + Lim[c][0], Lre[c][1] + Lim[c][1],
               Lre[c][2] + Lim[c][2], Lre[c][3] + Lim[c][3]);
    }
}

__global__ __launch_bounds__(128) void fwd_w(const float* __restrict__ w) {
    int idx = blockIdx.x * 128 + threadIdx.x;         // (o,i), i fastest
    float v[32];
    const float4* wv = reinterpret_cast<const float4*>(w) + (size_t)idx * 8;
    #pragma unroll
    for (int q = 0; q < 8; q++) {
        float4 t = wv[q];
        v[4*q] = t.x; v[4*q+1] = t.y; v[4*q+2] = t.z; v[4*q+3] = t.w;
    }
    float Wre[4][4] = {}, Wim[4][4] = {};
    fwall(v, Wre, Wim, std::make_integer_sequence<int, 32>{});
    int o = idx >> 8, i = idx & 255;
    #pragma unroll
    for (int t = 0; t < 4; t++) {
        size_t base = (size_t)(o * 4 + t) * KC + i * 4;
        *reinterpret_cast<uint2*>(g_B + base) =
            h4(Wre[t][0], Wre[t][1], Wre[t][2], Wre[t][3]);
        *reinterpret_cast<uint2*>(g_B + B_CHUNK + base) =
            h4(Wim[t][0], Wim[t][1], Wim[t][2], Wim[t][3]);
        *reinterpret_cast<uint2*>(g_B + 2 * B_CHUNK + base) =
            h4(Wre[t][0] + Wim[t][0], Wre[t][1] + Wim[t][1],
               Wre[t][2] + Wim[t][2], Wre[t][3] + Wim[t][3]);
    }
}

// ================= fused GEMM (fp16 HMMA) + Gauss + blades + normalize =================
__device__ __forceinline__ void load_stage(uint32_t sm, const __half* gA, const __half* gB,
                                           int it, int tid) {
    const int k0 = it * BK;
    #pragma unroll
    for (int r = 0; r < 8; r++) {
        int slot = tid + r * 256;          // 0..2047 (256 threads x 8)
        int row  = slot >> 3;              // 0..255 : rows 0-127 A, 128-255 B
        int c    = slot & 7;               // 16B chunk within 128B row
        uint32_t sw = (uint32_t)(((row & 127) * 128 + ((c ^ (row & 7)) << 4))
                                 + ((row >> 7) << 14));   // +16KB for B half
        const __half* src = (row < 128) ? (gA + (size_t)row * KC + k0 + c * 8)
                                        : (gB + (size_t)(row - 128) * KC + k0 + c * 8);
        cp16(sm + sw, src);
    }
}

// one pipelined K-loop (one Gauss product) accumulating into acc
__device__ __forceinline__ void gemm_z(float (&acc)[4][4][4],
                                       const __half* gA, const __half* gB,
                                       uint32_t sbase, int tid,
                                       uint32_t aRow, uint32_t bRow, int akb, int bkb, int lx) {
    load_stage(sbase, gA, gB, 0, tid);
    asm volatile("cp.async.commit_group;" ::: "memory");
    load_stage(sbase + STAGE_BYTES, gA, gB, 1, tid);
    asm volatile("cp.async.commit_group;" ::: "memory");

    #pragma unroll 1
    for (int it = 0; it < NIT; it++) {
        asm volatile("cp.async.wait_group 1;" ::: "memory");
        __syncthreads();
        int nx = it + STAGES - 1;
        if (nx < NIT)
            load_stage(sbase + (uint32_t)(nx % STAGES) * STAGE_BYTES, gA, gB, nx, tid);
        asm volatile("cp.async.commit_group;" ::: "memory");

        const uint32_t sm = sbase + (uint32_t)(it % STAGES) * STAGE_BYTES;
        #pragma unroll
        for (int ks = 0; ks < 4; ks++) {
            const uint32_t cA = (uint32_t)(((ks * 2 + akb) ^ lx) << 4);
            const uint32_t cB = (uint32_t)(((ks * 2 + bkb) ^ lx) << 4);
            uint32_t a[4][4], b[2][4];
            #pragma unroll
            for (int mi = 0; mi < 4; mi++)
                ldsm4(a[mi], sm + aRow + (uint32_t)(mi * 2048) + cA);
            #pragma unroll
            for (int p = 0; p < 2; p++)
                ldsm4(b[p], sm + bRow + (uint32_t)(p * 2048) + cB);
            #pragma unroll
            for (int mi = 0; mi < 4; mi++)
                #pragma unroll
                for (int p = 0; p < 2; p++) {
                    mma16(acc[mi][2 * p],     a[mi], b[p][0], b[p][1]);
                    mma16(acc[mi][2 * p + 1], a[mi], b[p][2], b[p][3]);
                }
        }
    }
    asm volatile("cp.async.wait_group 0;" ::: "memory");
    __syncthreads();   // all warps done with smem before next product reloads
}

#define SROW 132   // padded slab row stride (floats)

__global__ __launch_bounds__(256, 1)
void versor_fused(float* __restrict__ out) {
    extern __shared__ char smem[];
    const uint32_t sbase = smem_u32(smem);
    const int tid  = threadIdx.x;
    const int wid  = tid >> 5;
    const int lane = tid & 31;
    const int wm   = wid >> 2;     // 0..1 (64 M-rows each)
    const int wn   = wid & 3;      // 0..3 (32 N-cols each)

    const int N0 = blockIdx.x * BN;   // 8 n-tiles (fast: share A panel in L2)
    const int M0 = blockIdx.y * BM;   // 64 m-tiles

    // fragment geometry (b16 ldmatrix, m16n8k16 canonical)
    const int lx  = lane & 7;
    const int rA  = wm * 64 + lx + ((lane >> 3) & 1) * 8;
    const int akb = (lane >> 4) & 1;
    const int rB  = wn * 32 + lx + ((lane >> 4) & 1) * 8;
    const int bkb = (lane >> 3) & 1;
    const uint32_t aRow = (uint32_t)(rA * 128);
    const uint32_t bRow = 16384u + (uint32_t)(rB * 128);

    float acc0[4][4][4], acc1[4][4][4], acc2[4][4][4];
    #pragma unroll
    for (int mi = 0; mi < 4; mi++)
        #pragma unroll
        for (int nj = 0; nj < 4; nj++)
            #pragma unroll
            for (int q = 0; q < 4; q++) {
                acc0[mi][nj][q] = 0.0f; acc1[mi][nj][q] = 0.0f; acc2[mi][nj][q] = 0.0f;
            }

    // three Gauss products, sequential pipelined K-loops
    gemm_z(acc0, g_A + (size_t)M0 * KC,               g_B + (size_t)N0 * KC,
           sbase, tid, aRow, bRow, akb, bkb, lx);
    gemm_z(acc1, g_A + A_CHUNK + (size_t)M0 * KC,     g_B + B_CHUNK + (size_t)N0 * KC,
           sbase, tid, aRow, bRow, akb, bkb, lx);
    gemm_z(acc2, g_A + 2 * A_CHUNK + (size_t)M0 * KC, g_B + 2 * B_CHUNK + (size_t)N0 * KC,
           sbase, tid, aRow, bRow, akb, bkb, lx);

    // Gauss combine in registers: acc0 <- Re = P1 - P2 ; acc2 <- Im = P3 - P1 - P2
    #pragma unroll
    for (int mi = 0; mi < 4; mi++)
        #pragma unroll
        for (int nj = 0; nj < 4; nj++)
            #pragma unroll
            for (int q = 0; q < 4; q++) {
                float p1 = acc0[mi][nj][q], p2 = acc1[mi][nj][q], p3 = acc2[mi][nj][q];
                acc0[mi][nj][q] = p1 - p2;
                acc2[mi][nj][q] = p3 - p1 - p2;
            }

    // ---- epilogue: 4 slabs of 32 rows x 128 cols (re+im), blades + normalize ----
    float* Sre = reinterpret_cast<float*>(smem);          // [32][SROW]
    float* Sim = Sre + 32 * SROW;
    const int rofs = lane >> 2;      // 0..7
    const int qc   = lane & 3;       // col-pair

    #pragma unroll 1
    for (int s = 0; s < 4; s++) {
        __syncthreads();
        if (wm == (s >> 1)) {
            const int mib = (s & 1) * 2;
            #pragma unroll
            for (int dm = 0; dm < 2; dm++) {
                const int mi = mib + dm;
                const int rl = dm * 16 + rofs;
                #pragma unroll
                for (int nj = 0; nj < 4; nj++) {
                    const int cl = wn * 32 + nj * 8 + 2 * qc;
                    *reinterpret_cast<float2*>(&Sre[rl * SROW + cl]) =
                        make_float2(acc0[mi][nj][0], acc0[mi][nj][1]);
                    *reinterpret_cast<float2*>(&Sre[(rl + 8) * SROW + cl]) =
                        make_float2(acc0[mi][nj][2], acc0[mi][nj][3]);
                    *reinterpret_cast<float2*>(&Sim[rl * SROW + cl]) =
                        make_float2(acc2[mi][nj][0], acc2[mi][nj][1]);
                    *reinterpret_cast<float2*>(&Sim[(rl + 8) * SROW + cl]) =
                        make_float2(acc2[mi][nj][2], acc2[mi][nj][3]);
                }
            }
        }
        __syncthreads();

        // one (n,o) cell per thread: 8 n-groups x 32 o-groups
        const int nh = tid >> 5;     // 0..7
        const int oh = tid & 31;     // 0..31
        float Mre[4][4], Mim[4][4];
        #pragma unroll
        for (int c = 0; c < 4; c++) {
            float4 re = *reinterpret_cast<const float4*>(&Sre[(4 * nh + c) * SROW + 4 * oh]);
            float4 im = *reinterpret_cast<const float4*>(&Sim[(4 * nh + c) * SROW + 4 * oh]);
            Mre[0][c] = re.x; Mre[1][c] = re.y; Mre[2][c] = re.z; Mre[3][c] = re.w;
            Mim[0][c] = im.x; Mim[1][c] = im.y; Mim[2][c] = im.z; Mim[3][c] = im.w;
        }
        float v[32];
        blades(v, Mre, Mim, std::make_integer_sequence<int, 32>{});
        float ss = 1e-6f;
        #pragma unroll
        for (int k = 0; k < 32; k++) ss += v[k] * v[k];
        const float inv = rsqrtf(ss);

        const int n_global = (M0 >> 2) + s * 8 + nh;
        const int o_global = (N0 >> 2) + oh;
        float4* dst = reinterpret_cast<float4*>(out + ((size_t)n_global * 256 + o_global) * 32);
        #pragma unroll
        for (int q = 0; q < 8; q++)
            dst[q] = make_float4(v[4*q] * inv, v[4*q+1] * inv, v[4*q+2] * inv, v[4*q+3] * inv);
    }
}

// ================= host =================
extern "C" void kernel_launch(void* const* d_in, const int* in_sizes, int n_in,
                              void* d_out, int out_size) {
    const float* x = (const float*)d_in[0];   // [2048, 256, 32]
    const float* w = (const float*)d_in[1];   // [256, 256, 32]
    float* out = (float*)d_out;               // [2048, 256, 32]

    fwd_x<<<(NTOK * IFEAT) / 128, 128>>>(x);
    fwd_w<<<(OFEAT * IFEAT) / 128, 128>>>(w);

    cudaFuncSetAttribute(versor_fused, cudaFuncAttributeMaxDynamicSharedMemorySize, SMEM_TOTAL);
    dim3 grid(NC / BN, MDIM / BM);
    versor_fused<<<grid, 256, SMEM_TOTAL>>>(out);
}

// round 8
// speedup vs baseline: 1.4254x; 1.4254x over previous
#include <cuda_runtime.h>
#include <cuda_fp16.h>
#include <cstdint>
#include <utility>

#define NTOK 2048
#define IFEAT 256
#define OFEAT 256
#define MDIM 8192            // GEMM M = NTOK*4
#define NC   1024            // complex GEMM N
#define KC   1024            // complex GEMM K

#define BM 128
#define BN 128
#define BK 64                // 64 halfs = 128 B per smem row
#define STAGES 3
#define NIT (KC / BK)        // 16
#define STAGE_BYTES 32768    // A 16KB + B 16KB
#define SMEM_TOTAL (STAGES * STAGE_BYTES)

#define A_CHUNK ((size_t)MDIM * KC)   // halfs
#define B_CHUNK ((size_t)NC * KC)

// ---- scratch ----
__device__ __half g_A[3 * A_CHUNK];   // 48 MB: Xre, Xim, Xre+Xim  (fp16)
__device__ __half g_B[3 * B_CHUNK];   // 6 MB:  Wre, Wim, Wre+Wim

// ================= compile-time Cl(4,1) -> M4(C) representation =================
struct Rho { int col[32][4]; int code[32][4]; int s[32]; };

constexpr Rho make_rho() {
    Rho R{};
    int gc[5][4] = {}; int gv[5][4] = {};
    for (int r = 0; r < 4; r++) {
        int a = r >> 1, b = r & 1;
        gc[0][r] = r ^ 2; gv[0][r] = b ? 2 : 0;                              // s1 (x) E
        gc[1][r] = r ^ 2; gv[1][r] = ((a ? 1 : 3) + (b ? 2 : 0)) & 3;        // s2 (x) E
        gc[2][r] = r;     gv[2][r] = ((a ? 2 : 0) + (b ? 2 : 0)) & 3;        // s3 (x) E
        gc[3][r] = r ^ 1; gv[3][r] = 0;                                      // I (x) sx
        gc[4][r] = r ^ 1; gv[4][r] = b ? 2 : 0;                              // I (x) J
    }
    for (int A = 0; A < 32; A++) {
        int pc[4] = {0, 1, 2, 3}, pv[4] = {0, 0, 0, 0};
        for (int i = 0; i < 5; i++)
            if ((A >> i) & 1)
                for (int r = 0; r < 4; r++) {
                    int t = pc[r];
                    pc[r] = gc[i][t];
                    pv[r] = (pv[r] + gv[i][t]) & 3;
                }
        for (int r = 0; r < 4; r++) { R.col[A][r] = pc[r]; R.code[A][r] = pv[r]; }
        int sq = (pv[0] + pv[pc[0]]) & 3;
        R.s[A] = (sq == 0) ? 1 : -1;
    }
    return R;
}
constexpr Rho RHO = make_rho();

// ---- template-unrolled transforms ----
template<int A, int R>
__device__ __forceinline__ void fx1(const float* v, float (&Lre)[4][4], float (&Lim)[4][4]) {
    constexpr int c = RHO.col[A][R];
    constexpr int k = RHO.code[A][R];
    if constexpr (k == 0) Lre[c][R] += v[A];
    else if constexpr (k == 1) Lim[c][R] += v[A];
    else if constexpr (k == 2) Lre[c][R] -= v[A];
    else                       Lim[c][R] -= v[A];
}
template<int A>
__device__ __forceinline__ void fxA(const float* v, float (&Lre)[4][4], float (&Lim)[4][4]) {
    fx1<A,0>(v,Lre,Lim); fx1<A,1>(v,Lre,Lim); fx1<A,2>(v,Lre,Lim); fx1<A,3>(v,Lre,Lim);
}
template<int... As>
__device__ __forceinline__ void fxall(const float* v, float (&Lre)[4][4], float (&Lim)[4][4],
                                      std::integer_sequence<int, As...>) {
    (fxA<As>(v, Lre, Lim), ...);
}
template<int A, int R>
__device__ __forceinline__ void fw1(const float* v, float (&Wre)[4][4], float (&Wim)[4][4]) {
    constexpr int c = RHO.col[A][R];
    constexpr int k = RHO.code[A][R];
    if constexpr (k == 0) Wre[R][c] += v[A];
    else if constexpr (k == 1) Wim[R][c] += v[A];
    else if constexpr (k == 2) Wre[R][c] -= v[A];
    else                       Wim[R][c] -= v[A];
}
template<int A>
__device__ __forceinline__ void fwA(const float* v, float (&Wre)[4][4], float (&Wim)[4][4]) {
    fw1<A,0>(v,Wre,Wim); fw1<A,1>(v,Wre,Wim); fw1<A,2>(v,Wre,Wim); fw1<A,3>(v,Wre,Wim);
}
template<int... As>
__device__ __forceinline__ void fwall(const float* v, float (&Wre)[4][4], float (&Wim)[4][4],
                                      std::integer_sequence<int, As...>) {
    (fwA<As>(v, Wre, Wim), ...);
}
template<int A, int R>
__device__ __forceinline__ float iv1(const float (&Mre)[4][4], const float (&Mim)[4][4]) {
    constexpr int t = RHO.col[A][R];
    constexpr int k = RHO.code[A][R];
    if constexpr (k == 0) return  Mre[t][R];
    else if constexpr (k == 1) return -Mim[t][R];
    else if constexpr (k == 2) return -Mre[t][R];
    else                       return  Mim[t][R];
}
template<int A>
__device__ __forceinline__ float bladeA(const float (&Mre)[4][4], const float (&Mim)[4][4]) {
    constexpr float s = 0.25f * (float)RHO.s[A];
    return s * (iv1<A,0>(Mre,Mim) + iv1<A,1>(Mre,Mim) + iv1<A,2>(Mre,Mim) + iv1<A,3>(Mre,Mim));
}
template<int... As>
__device__ __forceinline__ void blades(float* v, const float (&Mre)[4][4], const float (&Mim)[4][4],
                                       std::integer_sequence<int, As...>) {
    ((v[As] = bladeA<As>(Mre, Mim)), ...);
}

// ================= PTX helpers =================
__device__ __forceinline__ uint32_t smem_u32(const void* p) {
    uint32_t a;
    asm("{ .reg .u64 t; cvta.to.shared.u64 t, %1; cvt.u32.u64 %0, t; }" : "=r"(a) : "l"(p));
    return a;
}
__device__ __forceinline__ void cp16(uint32_t s, const void* g) {
    asm volatile("cp.async.cg.shared.global [%0], [%1], 16;" :: "r"(s), "l"(g) : "memory");
}
__device__ __forceinline__ void ldsm4(uint32_t* r, uint32_t a) {
    asm volatile("ldmatrix.sync.aligned.m8n8.x4.shared.b16 {%0,%1,%2,%3}, [%4];"
        : "=r"(r[0]), "=r"(r[1]), "=r"(r[2]), "=r"(r[3]) : "r"(a));
}
__device__ __forceinline__ void mma16(float* d, const uint32_t* a, uint32_t b0, uint32_t b1) {
    asm volatile("mma.sync.aligned.m16n8k16.row.col.f32.f16.f16.f32 "
        "{%0,%1,%2,%3}, {%4,%5,%6,%7}, {%8,%9}, {%0,%1,%2,%3};"
        : "+f"(d[0]), "+f"(d[1]), "+f"(d[2]), "+f"(d[3])
        : "r"(a[0]), "r"(a[1]), "r"(a[2]), "r"(a[3]), "r"(b0), "r"(b1));
}
__device__ __forceinline__ uint2 h4(float a, float b, float c, float d) {
    __half2 lo = __floats2half2_rn(a, b);
    __half2 hi = __floats2half2_rn(c, d);
    uint2 r;
    r.x = *reinterpret_cast<uint32_t*>(&lo);
    r.y = *reinterpret_cast<uint32_t*>(&hi);
    return r;
}

// ================= transform kernels =================
__global__ __launch_bounds__(128) void fwd_x(const float* __restrict__ x) {
    int idx = blockIdx.x * 128 + threadIdx.x;         // (n,i), i fastest
    float v[32];
    const float4* xv = reinterpret_cast<const float4*>(x) + (size_t)idx * 8;
    #pragma unroll
    for (int q = 0; q < 8; q++) {
        float4 t = xv[q];
        v[4*q] = t.x; v[4*q+1] = t.y; v[4*q+2] = t.z; v[4*q+3] = t.w;
    }
    float Lre[4][4] = {}, Lim[4][4] = {};
    fxall(v, Lre, Lim, std::make_integer_sequence<int, 32>{});
    int n = idx >> 8, i = idx & 255;
    #pragma unroll
    for (int c = 0; c < 4; c++) {
        size_t base = (size_t)(n * 4 + c) * KC + i * 4;
        *reinterpret_cast<uint2*>(g_A + base) =
            h4(Lre[c][0], Lre[c][1], Lre[c][2], Lre[c][3]);
        *reinterpret_cast<uint2*>(g_A + A_CHUNK + base) =
            h4(Lim[c][0], Lim[c][1], Lim[c][2], Lim[c][3]);
        *reinterpret_cast<uint2*>(g_A + 2 * A_CHUNK + base) =
            h4(Lre[c][0] + Lim[c][0], Lre[c][1] + Lim[c][1],
               Lre[c][2] + Lim[c][2], Lre[c][3] + Lim[c][3]);
    }
}

__global__ __launch_bounds__(128) void fwd_w(const float* __restrict__ w) {
    int idx = blockIdx.x * 128 + threadIdx.x;         // (o,i), i fastest
    float v[32];
    const float4* wv = reinterpret_cast<const float4*>(w) + (size_t)idx * 8;
    #pragma unroll
    for (int q = 0; q < 8; q++) {
        float4 t = wv[q];
        v[4*q] = t.x; v[4*q+1] = t.y; v[4*q+2] = t.z; v[4*q+3] = t.w;
    }
    float Wre[4][4] = {}, Wim[4][4] = {};
    fwall(v, Wre, Wim, std::make_integer_sequence<int, 32>{});
    int o = idx >> 8, i = idx & 255;
    #pragma unroll
    for (int t = 0; t < 4; t++) {
        size_t base = (size_t)(o * 4 + t) * KC + i * 4;
        *reinterpret_cast<uint2*>(g_B + base) =
            h4(Wre[t][0], Wre[t][1], Wre[t][2], Wre[t][3]);
        *reinterpret_cast<uint2*>(g_B + B_CHUNK + base) =
            h4(Wim[t][0], Wim[t][1], Wim[t][2], Wim[t][3]);
        *reinterpret_cast<uint2*>(g_B + 2 * B_CHUNK + base) =
            h4(Wre[t][0] + Wim[t][0], Wre[t][1] + Wim[t][1],
               Wre[t][2] + Wim[t][2], Wre[t][3] + Wim[t][3]);
    }
}

// ================= fused GEMM (fp16 HMMA) + Gauss + blades + normalize =================
__device__ __forceinline__ void load_stage(uint32_t sm, const __half* gA, const __half* gB,
                                           int it, int tid) {
    const int k0 = it * BK;
    #pragma unroll
    for (int r = 0; r < 4; r++) {
        int slot = tid + r * 512;          // 0..2047 (512 threads x 4)
        int row  = slot >> 3;              // 0..255 : rows 0-127 A, 128-255 B
        int c    = slot & 7;               // 16B chunk within 128B row
        uint32_t sw = (uint32_t)(((row & 127) * 128 + ((c ^ (row & 7)) << 4))
                                 + ((row >> 7) << 14));   // +16KB for B half
        const __half* src = (row < 128) ? (gA + (size_t)row * KC + k0 + c * 8)
                                        : (gB + (size_t)(row - 128) * KC + k0 + c * 8);
        cp16(sm + sw, src);
    }
}

// one pipelined K-loop (one Gauss product), warp tile 32x32, acc[2][4][4]
__device__ __forceinline__ void gemm_z(float (&acc)[2][4][4],
                                       const __half* gA, const __half* gB,
                                       uint32_t sbase, int tid,
                                       uint32_t aRow, uint32_t bRow, int akb, int bkb, int lx) {
    load_stage(sbase, gA, gB, 0, tid);
    asm volatile("cp.async.commit_group;" ::: "memory");
    load_stage(sbase + STAGE_BYTES, gA, gB, 1, tid);
    asm volatile("cp.async.commit_group;" ::: "memory");

    #pragma unroll 1
    for (int it = 0; it < NIT; it++) {
        asm volatile("cp.async.wait_group 1;" ::: "memory");
        __syncthreads();
        int nx = it + STAGES - 1;
        if (nx < NIT)
            load_stage(sbase + (uint32_t)(nx % STAGES) * STAGE_BYTES, gA, gB, nx, tid);
        asm volatile("cp.async.commit_group;" ::: "memory");

        const uint32_t sm = sbase + (uint32_t)(it % STAGES) * STAGE_BYTES;
        #pragma unroll
        for (int ks = 0; ks < 4; ks++) {
            const uint32_t cA = (uint32_t)(((ks * 2 + akb) ^ lx) << 4);
            const uint32_t cB = (uint32_t)(((ks * 2 + bkb) ^ lx) << 4);
            uint32_t a[2][4], b[2][4];
            #pragma unroll
            for (int mi = 0; mi < 2; mi++)
                ldsm4(a[mi], sm + aRow + (uint32_t)(mi * 2048) + cA);   // 16 rows = 2KB
            #pragma unroll
            for (int p = 0; p < 2; p++)
                ldsm4(b[p], sm + bRow + (uint32_t)(p * 2048) + cB);
            #pragma unroll
            for (int mi = 0; mi < 2; mi++)
                #pragma unroll
                for (int p = 0; p < 2; p++) {
                    mma16(acc[mi][2 * p],     a[mi], b[p][0], b[p][1]);
                    mma16(acc[mi][2 * p + 1], a[mi], b[p][2], b[p][3]);
                }
        }
    }
    asm volatile("cp.async.wait_group 0;" ::: "memory");
    __syncthreads();   // all warps done with smem before next product reloads
}

#define SROW 132   // padded slab row stride (floats)

__global__ __launch_bounds__(512, 1)
void versor_fused(float* __restrict__ out) {
    extern __shared__ char smem[];
    const uint32_t sbase = smem_u32(smem);
    const int tid  = threadIdx.x;
    const int wid  = tid >> 5;
    const int lane = tid & 31;
    const int wm   = wid >> 2;     // 0..3 (32 M-rows each)
    const int wn   = wid & 3;      // 0..3 (32 N-cols each)

    const int N0 = blockIdx.x * BN;   // 8 n-tiles (fast: share A panel in L2)
    const int M0 = blockIdx.y * BM;   // 64 m-tiles

    // fragment geometry (b16 ldmatrix, m16n8k16 canonical)
    const int lx  = lane & 7;
    const int rA  = wm * 32 + lx + ((lane >> 3) & 1) * 8;
    const int akb = (lane >> 4) & 1;
    const int rB  = wn * 32 + lx + ((lane >> 4) & 1) * 8;
    const int bkb = (lane >> 3) & 1;
    const uint32_t aRow = (uint32_t)(rA * 128);
    const uint32_t bRow = 16384u + (uint32_t)(rB * 128);

    float acc0[2][4][4], acc1[2][4][4], acc2[2][4][4];
    #pragma unroll
    for (int mi = 0; mi < 2; mi++)
        #pragma unroll
        for (int nj = 0; nj < 4; nj++)
            #pragma unroll
            for (int q = 0; q < 4; q++) {
                acc0[mi][nj][q] = 0.0f; acc1[mi][nj][q] = 0.0f; acc2[mi][nj][q] = 0.0f;
            }

    // three Gauss products, sequential pipelined K-loops
    gemm_z(acc0, g_A + (size_t)M0 * KC,               g_B + (size_t)N0 * KC,
           sbase, tid, aRow, bRow, akb, bkb, lx);
    gemm_z(acc1, g_A + A_CHUNK + (size_t)M0 * KC,     g_B + B_CHUNK + (size_t)N0 * KC,
           sbase, tid, aRow, bRow, akb, bkb, lx);
    gemm_z(acc2, g_A + 2 * A_CHUNK + (size_t)M0 * KC, g_B + 2 * B_CHUNK + (size_t)N0 * KC,
           sbase, tid, aRow, bRow, akb, bkb, lx);

    // Gauss combine in registers: acc0 <- Re = P1 - P2 ; acc2 <- Im = P3 - P1 - P2
    #pragma unroll
    for (int mi = 0; mi < 2; mi++)
        #pragma unroll
        for (int nj = 0; nj < 4; nj++)
            #pragma unroll
            for (int q = 0; q < 4; q++) {
                float p1 = acc0[mi][nj][q], p2 = acc1[mi][nj][q], p3 = acc2[mi][nj][q];
                acc0[mi][nj][q] = p1 - p2;
                acc2[mi][nj][q] = p3 - p1 - p2;
            }

    // ---- epilogue: 4 slabs of 32 rows x 128 cols (re+im), blades + normalize ----
    float* Sre = reinterpret_cast<float*>(smem);          // [32][SROW]
    float* Sim = Sre + 32 * SROW;
    const int rofs = lane >> 2;      // 0..7
    const int qc   = lane & 3;       // col-pair

    #pragma unroll 1
    for (int s = 0; s < 4; s++) {
        __syncthreads();
        if (wm == s) {
            #pragma unroll
            for (int mi = 0; mi < 2; mi++) {
                const int rl = mi * 16 + rofs;
                #pragma unroll
                for (int nj = 0; nj < 4; nj++) {
                    const int cl = wn * 32 + nj * 8 + 2 * qc;
                    *reinterpret_cast<float2*>(&Sre[rl * SROW + cl]) =
                        make_float2(acc0[mi][nj][0], acc0[mi][nj][1]);
                    *reinterpret_cast<float2*>(&Sre[(rl + 8) * SROW + cl]) =
                        make_float2(acc0[mi][nj][2], acc0[mi][nj][3]);
                    *reinterpret_cast<float2*>(&Sim[rl * SROW + cl]) =
                        make_float2(acc2[mi][nj][0], acc2[mi][nj][1]);
                    *reinterpret_cast<float2*>(&Sim[(rl + 8) * SROW + cl]) =
                        make_float2(acc2[mi][nj][2], acc2[mi][nj][3]);
                }
            }
        }
        __syncthreads();

        // 256 cells per slab: 8 n-groups x 32 o-groups; threads 0-255 active
        if (tid < 256) {
            const int nh = tid >> 5;     // 0..7
            const int oh = tid & 31;     // 0..31
            float Mre[4][4], Mim[4][4];
            #pragma unroll
            for (int c = 0; c < 4; c++) {
                float4 re = *reinterpret_cast<const float4*>(&Sre[(4 * nh + c) * SROW + 4 * oh]);
                float4 im = *reinterpret_cast<const float4*>(&Sim[(4 * nh + c) * SROW + 4 * oh]);
                Mre[0][c] = re.x; Mre[1][c] = re.y; Mre[2][c] = re.z; Mre[3][c] = re.w;
                Mim[0][c] = im.x; Mim[1][c] = im.y; Mim[2][c] = im.z; Mim[3][c] = im.w;
            }
            float v[32];
            blades(v, Mre, Mim, std::make_integer_sequence<int, 32>{});
            float ss = 1e-6f;
            #pragma unroll
            for (int k = 0; k < 32; k++) ss += v[k] * v[k];
            const float inv = rsqrtf(ss);

            const int n_global = (M0 >> 2) + s * 8 + nh;
            const int o_global = (N0 >> 2) + oh;
            float4* dst = reinterpret_cast<float4*>(out + ((size_t)n_global * 256 + o_global) * 32);
            #pragma unroll
            for (int q = 0; q < 8; q++)
                dst[q] = make_float4(v[4*q] * inv, v[4*q+1] * inv, v[4*q+2] * inv, v[4*q+3] * inv);
        }
    }
}

// ================= host =================
extern "C" void kernel_launch(void* const* d_in, const int* in_sizes, int n_in,
                              void* d_out, int out_size) {
    const float* x = (const float*)d_in[0];   // [2048, 256, 32]
    const float* w = (const float*)d_in[1];   // [256, 256, 32]
    float* out = (float*)d_out;               // [2048, 256, 32]

    fwd_x<<<(NTOK * IFEAT) / 128, 128>>>(x);
    fwd_w<<<(OFEAT * IFEAT) / 128, 128>>>(w);

    cudaFuncSetAttribute(versor_fused, cudaFuncAttributeMaxDynamicSharedMemorySize, SMEM_TOTAL);
    dim3 grid(NC / BN, MDIM / BM);
    versor_fused<<<grid, 512, SMEM_TOTAL>>>(out);
}

// round 9
// speedup vs baseline: 1.4796x; 1.0380x over previous
#include <cuda_runtime.h>
#include <cuda_fp16.h>
#include <cstdint>
#include <utility>

#define NTOK 2048
#define IFEAT 256
#define OFEAT 256
#define MDIM 8192            // GEMM M = NTOK*4
#define NC   1024            // complex GEMM N
#define KC   1024            // complex GEMM K

#define BM 128
#define BN 128
#define BK 64                // 64 halfs = 128 B per smem row
#define STAGES 3
#define NIT (KC / BK)        // 16
#define STAGE_BYTES 32768    // A 16KB + B 16KB
#define PIPE_BYTES (STAGES * STAGE_BYTES)       // 98304
#define SROW 132             // padded tile row stride (floats)
#define TILE_BYTES (128 * SROW * 4)             // 67584
#define SMEM_TOTAL (PIPE_BYTES + TILE_BYTES)    // 165888

#define A_CHUNK ((size_t)MDIM * KC)   // halfs
#define B_CHUNK ((size_t)NC * KC)

// ---- scratch ----
__device__ __half g_A[3 * A_CHUNK];   // 48 MB: Xre, Xim, Xre+Xim  (fp16)
__device__ __half g_B[3 * B_CHUNK];   // 6 MB:  Wre, Wim, Wre+Wim

// ================= compile-time Cl(4,1) -> M4(C) representation =================
struct Rho { int col[32][4]; int code[32][4]; int s[32]; };

constexpr Rho make_rho() {
    Rho R{};
    int gc[5][4] = {}; int gv[5][4] = {};
    for (int r = 0; r < 4; r++) {
        int a = r >> 1, b = r & 1;
        gc[0][r] = r ^ 2; gv[0][r] = b ? 2 : 0;                              // s1 (x) E
        gc[1][r] = r ^ 2; gv[1][r] = ((a ? 1 : 3) + (b ? 2 : 0)) & 3;        // s2 (x) E
        gc[2][r] = r;     gv[2][r] = ((a ? 2 : 0) + (b ? 2 : 0)) & 3;        // s3 (x) E
        gc[3][r] = r ^ 1; gv[3][r] = 0;                                      // I (x) sx
        gc[4][r] = r ^ 1; gv[4][r] = b ? 2 : 0;                              // I (x) J
    }
    for (int A = 0; A < 32; A++) {
        int pc[4] = {0, 1, 2, 3}, pv[4] = {0, 0, 0, 0};
        for (int i = 0; i < 5; i++)
            if ((A >> i) & 1)
                for (int r = 0; r < 4; r++) {
                    int t = pc[r];
                    pc[r] = gc[i][t];
                    pv[r] = (pv[r] + gv[i][t]) & 3;
                }
        for (int r = 0; r < 4; r++) { R.col[A][r] = pc[r]; R.code[A][r] = pv[r]; }
        int sq = (pv[0] + pv[pc[0]]) & 3;
        R.s[A] = (sq == 0) ? 1 : -1;
    }
    return R;
}
constexpr Rho RHO = make_rho();

// ---- template-unrolled transforms ----
template<int A, int R>
__device__ __forceinline__ void fx1(const float* v, float (&Lre)[4][4], float (&Lim)[4][4]) {
    constexpr int c = RHO.col[A][R];
    constexpr int k = RHO.code[A][R];
    if constexpr (k == 0) Lre[c][R] += v[A];
    else if constexpr (k == 1) Lim[c][R] += v[A];
    else if constexpr (k == 2) Lre[c][R] -= v[A];
    else                       Lim[c][R] -= v[A];
}
template<int A>
__device__ __forceinline__ void fxA(const float* v, float (&Lre)[4][4], float (&Lim)[4][4]) {
    fx1<A,0>(v,Lre,Lim); fx1<A,1>(v,Lre,Lim); fx1<A,2>(v,Lre,Lim); fx1<A,3>(v,Lre,Lim);
}
template<int... As>
__device__ __forceinline__ void fxall(const float* v, float (&Lre)[4][4], float (&Lim)[4][4],
                                      std::integer_sequence<int, As...>) {
    (fxA<As>(v, Lre, Lim), ...);
}
template<int A, int R>
__device__ __forceinline__ void fw1(const float* v, float (&Wre)[4][4], float (&Wim)[4][4]) {
    constexpr int c = RHO.col[A][R];
    constexpr int k = RHO.code[A][R];
    if constexpr (k == 0) Wre[R][c] += v[A];
    else if constexpr (k == 1) Wim[R][c] += v[A];
    else if constexpr (k == 2) Wre[R][c] -= v[A];
    else                       Wim[R][c] -= v[A];
}
template<int A>
__device__ __forceinline__ void fwA(const float* v, float (&Wre)[4][4], float (&Wim)[4][4]) {
    fw1<A,0>(v,Wre,Wim); fw1<A,1>(v,Wre,Wim); fw1<A,2>(v,Wre,Wim); fw1<A,3>(v,Wre,Wim);
}
template<int... As>
__device__ __forceinline__ void fwall(const float* v, float (&Wre)[4][4], float (&Wim)[4][4],
                                      std::integer_sequence<int, As...>) {
    (fwA<As>(v, Wre, Wim), ...);
}
template<int A, int R>
__device__ __forceinline__ float iv1(const float (&Mre)[4][4], const float (&Mim)[4][4]) {
    constexpr int t = RHO.col[A][R];
    constexpr int k = RHO.code[A][R];
    if constexpr (k == 0) return  Mre[t][R];
    else if constexpr (k == 1) return -Mim[t][R];
    else if constexpr (k == 2) return -Mre[t][R];
    else                       return  Mim[t][R];
}
template<int A>
__device__ __forceinline__ float bladeA(const float (&Mre)[4][4], const float (&Mim)[4][4]) {
    constexpr float s = 0.25f * (float)RHO.s[A];
    return s * (iv1<A,0>(Mre,Mim) + iv1<A,1>(Mre,Mim) + iv1<A,2>(Mre,Mim) + iv1<A,3>(Mre,Mim));
}
template<int... As>
__device__ __forceinline__ void blades(float* v, const float (&Mre)[4][4], const float (&Mim)[4][4],
                                       std::integer_sequence<int, As...>) {
    ((v[As] = bladeA<As>(Mre, Mim)), ...);
}

// ================= PTX helpers =================
__device__ __forceinline__ uint32_t smem_u32(const void* p) {
    uint32_t a;
    asm("{ .reg .u64 t; cvta.to.shared.u64 t, %1; cvt.u32.u64 %0, t; }" : "=r"(a) : "l"(p));
    return a;
}
__device__ __forceinline__ void cp16(uint32_t s, const void* g) {
    asm volatile("cp.async.cg.shared.global [%0], [%1], 16;" :: "r"(s), "l"(g) : "memory");
}
__device__ __forceinline__ void ldsm4(uint32_t* r, uint32_t a) {
    asm volatile("ldmatrix.sync.aligned.m8n8.x4.shared.b16 {%0,%1,%2,%3}, [%4];"
        : "=r"(r[0]), "=r"(r[1]), "=r"(r[2]), "=r"(r[3]) : "r"(a));
}
__device__ __forceinline__ void mma16(float* d, const uint32_t* a, uint32_t b0, uint32_t b1) {
    asm volatile("mma.sync.aligned.m16n8k16.row.col.f32.f16.f16.f32 "
        "{%0,%1,%2,%3}, {%4,%5,%6,%7}, {%8,%9}, {%0,%1,%2,%3};"
        : "+f"(d[0]), "+f"(d[1]), "+f"(d[2]), "+f"(d[3])
        : "r"(a[0]), "r"(a[1]), "r"(a[2]), "r"(a[3]), "r"(b0), "r"(b1));
}
__device__ __forceinline__ uint2 h4(float a, float b, float c, float d) {
    __half2 lo = __floats2half2_rn(a, b);
    __half2 hi = __floats2half2_rn(c, d);
    uint2 r;
    r.x = *reinterpret_cast<uint32_t*>(&lo);
    r.y = *reinterpret_cast<uint32_t*>(&hi);
    return r;
}

// ================= transform kernels =================
__global__ __launch_bounds__(128) void fwd_x(const float* __restrict__ x) {
    int idx = blockIdx.x * 128 + threadIdx.x;         // (n,i), i fastest
    float v[32];
    const float4* xv = reinterpret_cast<const float4*>(x) + (size_t)idx * 8;
    #pragma unroll
    for (int q = 0; q < 8; q++) {
        float4 t = xv[q];
        v[4*q] = t.x; v[4*q+1] = t.y; v[4*q+2] = t.z; v[4*q+3] = t.w;
    }
    float Lre[4][4] = {}, Lim[4][4] = {};
    fxall(v, Lre, Lim, std::make_integer_sequence<int, 32>{});
    int n = idx >> 8, i = idx & 255;
    #pragma unroll
    for (int c = 0; c < 4; c++) {
        size_t base = (size_t)(n * 4 + c) * KC + i * 4;
        *reinterpret_cast<uint2*>(g_A + base) =
            h4(Lre[c][0], Lre[c][1], Lre[c][2], Lre[c][3]);
        *reinterpret_cast<uint2*>(g_A + A_CHUNK + base) =
            h4(Lim[c][0], Lim[c][1], Lim[c][2], Lim[c][3]);
        *reinterpret_cast<uint2*>(g_A + 2 * A_CHUNK + base) =
            h4(Lre[c][0] + Lim[c][0], Lre[c][1] + Lim[c][1],
               Lre[c][2] + Lim[c][2], Lre[c][3] + Lim[c][3]);
    }
}

__global__ __launch_bounds__(128) void fwd_w(const float* __restrict__ w) {
    int idx = blockIdx.x * 128 + threadIdx.x;         // (o,i), i fastest
    float v[32];
    const float4* wv = reinterpret_cast<const float4*>(w) + (size_t)idx * 8;
    #pragma unroll
    for (int q = 0; q < 8; q++) {
        float4 t = wv[q];
        v[4*q] = t.x; v[4*q+1] = t.y; v[4*q+2] = t.z; v[4*q+3] = t.w;
    }
    float Wre[4][4] = {}, Wim[4][4] = {};
    fwall(v, Wre, Wim, std::make_integer_sequence<int, 32>{});
    int o = idx >> 8, i = idx & 255;
    #pragma unroll
    for (int t = 0; t < 4; t++) {
        size_t base = (size_t)(o * 4 + t) * KC + i * 4;
        *reinterpret_cast<uint2*>(g_B + base) =
            h4(Wre[t][0], Wre[t][1], Wre[t][2], Wre[t][3]);
        *reinterpret_cast<uint2*>(g_B + B_CHUNK + base) =
            h4(Wim[t][0], Wim[t][1], Wim[t][2], Wim[t][3]);
        *reinterpret_cast<uint2*>(g_B + 2 * B_CHUNK + base) =
            h4(Wre[t][0] + Wim[t][0], Wre[t][1] + Wim[t][1],
               Wre[t][2] + Wim[t][2], Wre[t][3] + Wim[t][3]);
    }
}

// ================= fused GEMM (fp16 HMMA) + Gauss + blades + normalize =================
__device__ __forceinline__ void load_stage(uint32_t sm, const __half* gA, const __half* gB,
                                           int it, int tid) {
    const int k0 = it * BK;
    #pragma unroll
    for (int r = 0; r < 8; r++) {
        int slot = tid + r * 256;          // 0..2047 (256 threads x 8)
        int row  = slot >> 3;              // 0..255 : rows 0-127 A, 128-255 B
        int c    = slot & 7;               // 16B chunk within 128B row
        uint32_t sw = (uint32_t)(((row & 127) * 128 + ((c ^ (row & 7)) << 4))
                                 + ((row >> 7) << 14));   // +16KB for B half
        const __half* src = (row < 128) ? (gA + (size_t)row * KC + k0 + c * 8)
                                        : (gB + (size_t)(row - 128) * KC + k0 + c * 8);
        cp16(sm + sw, src);
    }
}

// one pipelined K-loop (one Gauss product), warp tile 64x32, acc[4][4][4]
__device__ __forceinline__ void gemm_z(float (&acc)[4][4][4],
                                       const __half* gA, const __half* gB,
                                       uint32_t sbase, int tid,
                                       uint32_t aRow, uint32_t bRow, int akb, int bkb, int lx) {
    load_stage(sbase, gA, gB, 0, tid);
    asm volatile("cp.async.commit_group;" ::: "memory");
    load_stage(sbase + STAGE_BYTES, gA, gB, 1, tid);
    asm volatile("cp.async.commit_group;" ::: "memory");

    #pragma unroll 1
    for (int it = 0; it < NIT; it++) {
        asm volatile("cp.async.wait_group 1;" ::: "memory");
        __syncthreads();
        int nx = it + STAGES - 1;
        if (nx < NIT)
            load_stage(sbase + (uint32_t)(nx % STAGES) * STAGE_BYTES, gA, gB, nx, tid);
        asm volatile("cp.async.commit_group;" ::: "memory");

        const uint32_t sm = sbase + (uint32_t)(it % STAGES) * STAGE_BYTES;
        #pragma unroll
        for (int ks = 0; ks < 4; ks++) {
            const uint32_t cA = (uint32_t)(((ks * 2 + akb) ^ lx) << 4);
            const uint32_t cB = (uint32_t)(((ks * 2 + bkb) ^ lx) << 4);
            uint32_t a[4][4], b[2][4];
            #pragma unroll
            for (int mi = 0; mi < 4; mi++)
                ldsm4(a[mi], sm + aRow + (uint32_t)(mi * 2048) + cA);   // 16 rows = 2KB
            #pragma unroll
            for (int p = 0; p < 2; p++)
                ldsm4(b[p], sm + bRow + (uint32_t)(p * 2048) + cB);
            #pragma unroll
            for (int mi = 0; mi < 4; mi++)
                #pragma unroll
                for (int p = 0; p < 2; p++) {
                    mma16(acc[mi][2 * p],     a[mi], b[p][0], b[p][1]);
                    mma16(acc[mi][2 * p + 1], a[mi], b[p][2], b[p][3]);
                }
        }
    }
    asm volatile("cp.async.wait_group 0;" ::: "memory");
    __syncthreads();   // pipeline smem dead after this
}

__device__ __forceinline__ void zero_acc(float (&acc)[4][4][4]) {
    #pragma unroll
    for (int mi = 0; mi < 4; mi++)
        #pragma unroll
        for (int nj = 0; nj < 4; nj++)
            #pragma unroll
            for (int q = 0; q < 4; q++) acc[mi][nj][q] = 0.0f;
}

__global__ __launch_bounds__(256, 1)
void versor_fused(float* __restrict__ out) {
    extern __shared__ char smem[];
    const uint32_t sbase = smem_u32(smem);
    const int tid  = threadIdx.x;
    const int wid  = tid >> 5;
    const int lane = tid & 31;
    const int wm   = wid >> 2;     // 0..1 (64 M-rows each)
    const int wn   = wid & 3;      // 0..3 (32 N-cols each)

    const int N0 = blockIdx.x * BN;   // 8 n-tiles (fast: share A panel in L2)
    const int M0 = blockIdx.y * BM;   // 64 m-tiles

    // fragment geometry (b16 ldmatrix, m16n8k16 canonical)
    const int lx  = lane & 7;
    const int rA  = wm * 64 + lx + ((lane >> 3) & 1) * 8;
    const int akb = (lane >> 4) & 1;
    const int rB  = wn * 32 + lx + ((lane >> 4) & 1) * 8;
    const int bkb = (lane >> 3) & 1;
    const uint32_t aRow = (uint32_t)(rA * 128);
    const uint32_t bRow = 16384u + (uint32_t)(rB * 128);

    // smem regions: pipeline [0, PIPE_BYTES) ; stash/Im tile S [PIPE_BYTES, +TILE_BYTES)
    // Re tile R overlaps the (dead) pipeline region after the last K-loop.
    float* S = reinterpret_cast<float*>(smem + PIPE_BYTES);  // [128][SROW]
    float* R = reinterpret_cast<float*>(smem);               // [128][SROW]

    // fragment scatter coordinates (per thread)
    const int rofs = lane >> 2;      // 0..7
    const int qc   = lane & 3;       // col-pair

    float accA[4][4][4], accB[4][4][4];

    // ---- product P3 = (Xre+Xim)(Wre+Wim)^T ----
    zero_acc(accA);
    gemm_z(accA, g_A + 2 * A_CHUNK + (size_t)M0 * KC, g_B + 2 * B_CHUNK + (size_t)N0 * KC,
           sbase, tid, aRow, bRow, akb, bkb, lx);
    // stash P3 to S (per-thread disjoint positions; re-read by same thread later)
    #pragma unroll
    for (int mi = 0; mi < 4; mi++) {
        const int rl = wm * 64 + mi * 16 + rofs;
        #pragma unroll
        for (int nj = 0; nj < 4; nj++) {
            const int cl = wn * 32 + nj * 8 + 2 * qc;
            *reinterpret_cast<float2*>(&S[rl * SROW + cl]) =
                make_float2(accA[mi][nj][0], accA[mi][nj][1]);
            *reinterpret_cast<float2*>(&S[(rl + 8) * SROW + cl]) =
                make_float2(accA[mi][nj][2], accA[mi][nj][3]);
        }
    }

    // ---- product P1 = Xre . Wre^T ----
    zero_acc(accA);
    gemm_z(accA, g_A + (size_t)M0 * KC, g_B + (size_t)N0 * KC,
           sbase, tid, aRow, bRow, akb, bkb, lx);

    // ---- product P2 = Xim . Wim^T ----
    zero_acc(accB);
    gemm_z(accB, g_A + A_CHUNK + (size_t)M0 * KC, g_B + B_CHUNK + (size_t)N0 * KC,
           sbase, tid, aRow, bRow, akb, bkb, lx);

    // ---- combine: R <- Re = P1 - P2 ; S <- Im = P3 - P1 - P2 (in place) ----
    #pragma unroll
    for (int mi = 0; mi < 4; mi++) {
        const int rl = wm * 64 + mi * 16 + rofs;
        #pragma unroll
        for (int nj = 0; nj < 4; nj++) {
            const int cl = wn * 32 + nj * 8 + 2 * qc;
            #pragma unroll
            for (int h = 0; h < 2; h++) {
                const int rr = rl + h * 8;
                const float p1a = accA[mi][nj][2*h],   p2a = accB[mi][nj][2*h];
                const float p1b = accA[mi][nj][2*h+1], p2b = accB[mi][nj][2*h+1];
                *reinterpret_cast<float2*>(&R[rr * SROW + cl]) =
                    make_float2(p1a - p2a, p1b - p2b);
                float2 p3 = *reinterpret_cast<float2*>(&S[rr * SROW + cl]);
                *reinterpret_cast<float2*>(&S[rr * SROW + cl]) =
                    make_float2(p3.x - p1a - p2a, p3.y - p1b - p2b);
            }
        }
    }
    __syncthreads();

    // ---- epilogue: blades + normalize, 4 cells/thread ----
    #pragma unroll
    for (int e = 0; e < 4; e++) {
        const int cell = tid + e * 256;      // 0..1023
        const int t = cell >> 5;             // token within tile 0..31
        const int g = cell & 31;             // o-group 0..31
        float Mre[4][4], Mim[4][4];
        #pragma unroll
        for (int c = 0; c < 4; c++) {
            float4 re = *reinterpret_cast<const float4*>(&R[(4 * t + c) * SROW + 4 * g]);
            float4 im = *reinterpret_cast<const float4*>(&S[(4 * t + c) * SROW + 4 * g]);
            Mre[0][c] = re.x; Mre[1][c] = re.y; Mre[2][c] = re.z; Mre[3][c] = re.w;
            Mim[0][c] = im.x; Mim[1][c] = im.y; Mim[2][c] = im.z; Mim[3][c] = im.w;
        }
        float v[32];
        blades(v, Mre, Mim, std::make_integer_sequence<int, 32>{});
        float ss = 1e-6f;
        #pragma unroll
        for (int k = 0; k < 32; k++) ss += v[k] * v[k];
        const float inv = rsqrtf(ss);

        const int n_global = (M0 >> 2) + t;
        const int o_global = (N0 >> 2) + g;
        float4* dst = reinterpret_cast<float4*>(out + ((size_t)n_global * 256 + o_global) * 32);
        #pragma unroll
        for (int q = 0; q < 8; q++)
            dst[q] = make_float4(v[4*q] * inv, v[4*q+1] * inv, v[4*q+2] * inv, v[4*q+3] * inv);
    }
}

// ================= host =================
extern "C" void kernel_launch(void* const* d_in, const int* in_sizes, int n_in,
                              void* d_out, int out_size) {
    const float* x = (const float*)d_in[0];   // [2048, 256, 32]
    const float* w = (const float*)d_in[1];   // [256, 256, 32]
    float* out = (float*)d_out;               // [2048, 256, 32]

    fwd_x<<<(NTOK * IFEAT) / 128, 128>>>(x);
    fwd_w<<<(OFEAT * IFEAT) / 128, 128>>>(w);

    cudaFuncSetAttribute(versor_fused, cudaFuncAttributeMaxDynamicSharedMemorySize, SMEM_TOTAL);
    dim3 grid(NC / BN, MDIM / BM);
    versor_fused<<<grid, 256, SMEM_TOTAL>>>(out);
}

// round 10
// speedup vs baseline: 1.7845x; 1.2061x over previous
#include <cuda_runtime.h>
#include <cuda_fp16.h>
#include <cstdint>
#include <utility>

#define NTOK 2048
#define IFEAT 256
#define OFEAT 256
#define MDIM 8192            // GEMM M = NTOK*4
#define NC   1024            // complex GEMM N
#define KC   1024            // complex GEMM K

#define BM 128
#define BN 128
#define BK 64                // 64 halfs = 128 B per smem row
#define STAGES 3
#define NIT (KC / BK)        // 16
#define STAGE_BYTES 32768    // A 16KB + B 16KB
#define PIPE_BYTES (STAGES * STAGE_BYTES)   // 98304
#define FLAG_OFF PIPE_BYTES
#define SMEM_TOTAL (PIPE_BYTES + 128)       // 98432 -> 2 CTAs/SM
#define SROW 132             // stash row stride (floats); stash overlays dead pipeline

#define A_CHUNK ((size_t)MDIM * KC)   // halfs
#define B_CHUNK ((size_t)NC * KC)
#define P_CHUNK ((size_t)MDIM * NC)   // floats

// ---- scratch ----
__device__ __half g_A[3 * A_CHUNK];   // 48 MB: Xre, Xim, Xre+Xim  (fp16)
__device__ __half g_B[3 * B_CHUNK];   // 6 MB:  Wre, Wim, Wre+Wim
__device__ float  g_P[3 * P_CHUNK];   // 96 MB: P1, P2, P3 (fp32)
__device__ unsigned g_cnt[512];       // per-tile arrival counters (zero-init; self-resetting)

// ================= compile-time Cl(4,1) -> M4(C) representation =================
struct Rho { int col[32][4]; int code[32][4]; int s[32]; };

constexpr Rho make_rho() {
    Rho R{};
    int gc[5][4] = {}; int gv[5][4] = {};
    for (int r = 0; r < 4; r++) {
        int a = r >> 1, b = r & 1;
        gc[0][r] = r ^ 2; gv[0][r] = b ? 2 : 0;                              // s1 (x) E
        gc[1][r] = r ^ 2; gv[1][r] = ((a ? 1 : 3) + (b ? 2 : 0)) & 3;        // s2 (x) E
        gc[2][r] = r;     gv[2][r] = ((a ? 2 : 0) + (b ? 2 : 0)) & 3;        // s3 (x) E
        gc[3][r] = r ^ 1; gv[3][r] = 0;                                      // I (x) sx
        gc[4][r] = r ^ 1; gv[4][r] = b ? 2 : 0;                              // I (x) J
    }
    for (int A = 0; A < 32; A++) {
        int pc[4] = {0, 1, 2, 3}, pv[4] = {0, 0, 0, 0};
        for (int i = 0; i < 5; i++)
            if ((A >> i) & 1)
                for (int r = 0; r < 4; r++) {
                    int t = pc[r];
                    pc[r] = gc[i][t];
                    pv[r] = (pv[r] + gv[i][t]) & 3;
                }
        for (int r = 0; r < 4; r++) { R.col[A][r] = pc[r]; R.code[A][r] = pv[r]; }
        int sq = (pv[0] + pv[pc[0]]) & 3;
        R.s[A] = (sq == 0) ? 1 : -1;
    }
    return R;
}
constexpr Rho RHO = make_rho();

// ---- template-unrolled transforms ----
template<int A, int R>
__device__ __forceinline__ void fx1(const float* v, float (&Lre)[4][4], float (&Lim)[4][4]) {
    constexpr int c = RHO.col[A][R];
    constexpr int k = RHO.code[A][R];
    if constexpr (k == 0) Lre[c][R] += v[A];
    else if constexpr (k == 1) Lim[c][R] += v[A];
    else if constexpr (k == 2) Lre[c][R] -= v[A];
    else                       Lim[c][R] -= v[A];
}
template<int A>
__device__ __forceinline__ void fxA(const float* v, float (&Lre)[4][4], float (&Lim)[4][4]) {
    fx1<A,0>(v,Lre,Lim); fx1<A,1>(v,Lre,Lim); fx1<A,2>(v,Lre,Lim); fx1<A,3>(v,Lre,Lim);
}
template<int... As>
__device__ __forceinline__ void fxall(const float* v, float (&Lre)[4][4], float (&Lim)[4][4],
                                      std::integer_sequence<int, As...>) {
    (fxA<As>(v, Lre, Lim), ...);
}
template<int A, int R>
__device__ __forceinline__ void fw1(const float* v, float (&Wre)[4][4], float (&Wim)[4][4]) {
    constexpr int c = RHO.col[A][R];
    constexpr int k = RHO.code[A][R];
    if constexpr (k == 0) Wre[R][c] += v[A];
    else if constexpr (k == 1) Wim[R][c] += v[A];
    else if constexpr (k == 2) Wre[R][c] -= v[A];
    else                       Wim[R][c] -= v[A];
}
template<int A>
__device__ __forceinline__ void fwA(const float* v, float (&Wre)[4][4], float (&Wim)[4][4]) {
    fw1<A,0>(v,Wre,Wim); fw1<A,1>(v,Wre,Wim); fw1<A,2>(v,Wre,Wim); fw1<A,3>(v,Wre,Wim);
}
template<int... As>
__device__ __forceinline__ void fwall(const float* v, float (&Wre)[4][4], float (&Wim)[4][4],
                                      std::integer_sequence<int, As...>) {
    (fwA<As>(v, Wre, Wim), ...);
}
template<int A, int R>
__device__ __forceinline__ float iv1(const float (&Mre)[4][4], const float (&Mim)[4][4]) {
    constexpr int t = RHO.col[A][R];
    constexpr int k = RHO.code[A][R];
    if constexpr (k == 0) return  Mre[t][R];
    else if constexpr (k == 1) return -Mim[t][R];
    else if constexpr (k == 2) return -Mre[t][R];
    else                       return  Mim[t][R];
}
template<int A>
__device__ __forceinline__ float bladeA(const float (&Mre)[4][4], const float (&Mim)[4][4]) {
    constexpr float s = 0.25f * (float)RHO.s[A];
    return s * (iv1<A,0>(Mre,Mim) + iv1<A,1>(Mre,Mim) + iv1<A,2>(Mre,Mim) + iv1<A,3>(Mre,Mim));
}
template<int... As>
__device__ __forceinline__ void blades(float* v, const float (&Mre)[4][4], const float (&Mim)[4][4],
                                       std::integer_sequence<int, As...>) {
    ((v[As] = bladeA<As>(Mre, Mim)), ...);
}

// ================= PTX helpers =================
__device__ __forceinline__ uint32_t smem_u32(const void* p) {
    uint32_t a;
    asm("{ .reg .u64 t; cvta.to.shared.u64 t, %1; cvt.u32.u64 %0, t; }" : "=r"(a) : "l"(p));
    return a;
}
__device__ __forceinline__ void cp16(uint32_t s, const void* g) {
    asm volatile("cp.async.cg.shared.global [%0], [%1], 16;" :: "r"(s), "l"(g) : "memory");
}
__device__ __forceinline__ void ldsm4(uint32_t* r, uint32_t a) {
    asm volatile("ldmatrix.sync.aligned.m8n8.x4.shared.b16 {%0,%1,%2,%3}, [%4];"
        : "=r"(r[0]), "=r"(r[1]), "=r"(r[2]), "=r"(r[3]) : "r"(a));
}
__device__ __forceinline__ void mma16(float* d, const uint32_t* a, uint32_t b0, uint32_t b1) {
    asm volatile("mma.sync.aligned.m16n8k16.row.col.f32.f16.f16.f32 "
        "{%0,%1,%2,%3}, {%4,%5,%6,%7}, {%8,%9}, {%0,%1,%2,%3};"
        : "+f"(d[0]), "+f"(d[1]), "+f"(d[2]), "+f"(d[3])
        : "r"(a[0]), "r"(a[1]), "r"(a[2]), "r"(a[3]), "r"(b0), "r"(b1));
}
__device__ __forceinline__ uint2 h4(float a, float b, float c, float d) {
    __half2 lo = __floats2half2_rn(a, b);
    __half2 hi = __floats2half2_rn(c, d);
    uint2 r;
    r.x = *reinterpret_cast<uint32_t*>(&lo);
    r.y = *reinterpret_cast<uint32_t*>(&hi);
    return r;
}

// ================= transform kernels =================
__global__ __launch_bounds__(128) void fwd_x(const float* __restrict__ x) {
    int idx = blockIdx.x * 128 + threadIdx.x;         // (n,i), i fastest
    float v[32];
    const float4* xv = reinterpret_cast<const float4*>(x) + (size_t)idx * 8;
    #pragma unroll
    for (int q = 0; q < 8; q++) {
        float4 t = xv[q];
        v[4*q] = t.x; v[4*q+1] = t.y; v[4*q+2] = t.z; v[4*q+3] = t.w;
    }
    float Lre[4][4] = {}, Lim[4][4] = {};
    fxall(v, Lre, Lim, std::make_integer_sequence<int, 32>{});
    int n = idx >> 8, i = idx & 255;
    #pragma unroll
    for (int c = 0; c < 4; c++) {
        size_t base = (size_t)(n * 4 + c) * KC + i * 4;
        *reinterpret_cast<uint2*>(g_A + base) =
            h4(Lre[c][0], Lre[c][1], Lre[c][2], Lre[c][3]);
        *reinterpret_cast<uint2*>(g_A + A_CHUNK + base) =
            h4(Lim[c][0], Lim[c][1], Lim[c][2], Lim[c][3]);
        *reinterpret_cast<uint2*>(g_A + 2 * A_CHUNK + base) =
            h4(Lre[c][0] + Lim[c][0], Lre[c][1] + Lim[c][1],
               Lre[c][2] + Lim[c][2], Lre[c][3] + Lim[c][3]);
    }
}

__global__ __launch_bounds__(128) void fwd_w(const float* __restrict__ w) {
    int idx = blockIdx.x * 128 + threadIdx.x;         // (o,i), i fastest
    float v[32];
    const float4* wv = reinterpret_cast<const float4*>(w) + (size_t)idx * 8;
    #pragma unroll
    for (int q = 0; q < 8; q++) {
        float4 t = wv[q];
        v[4*q] = t.x; v[4*q+1] = t.y; v[4*q+2] = t.z; v[4*q+3] = t.w;
    }
    float Wre[4][4] = {}, Wim[4][4] = {};
    fwall(v, Wre, Wim, std::make_integer_sequence<int, 32>{});
    int o = idx >> 8, i = idx & 255;
    #pragma unroll
    for (int t = 0; t < 4; t++) {
        size_t base = (size_t)(o * 4 + t) * KC + i * 4;
        *reinterpret_cast<uint2*>(g_B + base) =
            h4(Wre[t][0], Wre[t][1], Wre[t][2], Wre[t][3]);
        *reinterpret_cast<uint2*>(g_B + B_CHUNK + base) =
            h4(Wim[t][0], Wim[t][1], Wim[t][2], Wim[t][3]);
        *reinterpret_cast<uint2*>(g_B + 2 * B_CHUNK + base) =
            h4(Wre[t][0] + Wim[t][0], Wre[t][1] + Wim[t][1],
               Wre[t][2] + Wim[t][2], Wre[t][3] + Wim[t][3]);
    }
}

// ================= GEMM (round-6 mainloop) + last-sibling fused epilogue =================
__device__ __forceinline__ void load_stage(uint32_t sm, const __half* gA, const __half* gB,
                                           int it, int tid) {
    const int k0 = it * BK;
    #pragma unroll
    for (int r = 0; r < 8; r++) {
        int slot = tid + r * 128;          // 0..1023
        int row  = slot >> 3;              // 0..127
        int c    = slot & 7;               // 16B chunk within 128B row
        uint32_t sw = (uint32_t)(row * 128 + ((c ^ (row & 7)) << 4));
        cp16(sm + sw,         gA + (size_t)row * KC + k0 + c * 8);
        cp16(sm + 16384 + sw, gB + (size_t)row * KC + k0 + c * 8);
    }
}

__global__ __launch_bounds__(128, 2)
void versor_mma(float* __restrict__ out) {
    extern __shared__ char smem[];
    const uint32_t sbase = smem_u32(smem);
    const int tid  = threadIdx.x;
    const int wid  = tid >> 5;
    const int lane = tid & 31;
    const int wm   = wid & 1;
    const int wn   = wid >> 1;

    const int z     = blockIdx.x % 3;      // Gauss product; siblings adjacent in x
    const int ntile = blockIdx.x / 3;      // 8 n-tiles
    const int mtile = blockIdx.y;          // 64 m-tiles
    const int M0 = mtile * BM;
    const int N0 = ntile * BN;
    const int tileid = mtile * 8 + ntile;

    const __half* gA = g_A + (size_t)z * A_CHUNK + (size_t)M0 * KC;
    const __half* gB = g_B + (size_t)z * B_CHUNK + (size_t)N0 * KC;
    float* gP = g_P + (size_t)z * P_CHUNK;

    const int lx  = lane & 7;
    const int rA  = wm * 64 + lx + ((lane >> 3) & 1) * 8;
    const int akb = (lane >> 4) & 1;
    const int rB  = wn * 64 + lx + ((lane >> 4) & 1) * 8;
    const int bkb = (lane >> 3) & 1;
    const uint32_t aRow = (uint32_t)(rA * 128);
    const uint32_t bRow = 16384u + (uint32_t)(rB * 128);

    float acc[4][8][4];
    #pragma unroll
    for (int mi = 0; mi < 4; mi++)
        #pragma unroll
        for (int nj = 0; nj < 8; nj++)
            #pragma unroll
            for (int q = 0; q < 4; q++) acc[mi][nj][q] = 0.0f;

    load_stage(sbase, gA, gB, 0, tid);
    asm volatile("cp.async.commit_group;" ::: "memory");
    load_stage(sbase + STAGE_BYTES, gA, gB, 1, tid);
    asm volatile("cp.async.commit_group;" ::: "memory");

    #pragma unroll 1
    for (int it = 0; it < NIT; it++) {
        asm volatile("cp.async.wait_group 1;" ::: "memory");
        __syncthreads();
        int nx = it + STAGES - 1;
        if (nx < NIT)
            load_stage(sbase + (uint32_t)(nx % STAGES) * STAGE_BYTES, gA, gB, nx, tid);
        asm volatile("cp.async.commit_group;" ::: "memory");

        const uint32_t sm = sbase + (uint32_t)(it % STAGES) * STAGE_BYTES;
        #pragma unroll
        for (int ks = 0; ks < 4; ks++) {
            const uint32_t cA = (uint32_t)(((ks * 2 + akb) ^ lx) << 4);
            const uint32_t cB = (uint32_t)(((ks * 2 + bkb) ^ lx) << 4);
            uint32_t a[4][4], b[4][4];
            #pragma unroll
            for (int mi = 0; mi < 4; mi++)
                ldsm4(a[mi], sm + aRow + (uint32_t)(mi * 2048) + cA);
            #pragma unroll
            for (int nj2 = 0; nj2 < 4; nj2++)
                ldsm4(b[nj2], sm + bRow + (uint32_t)(nj2 * 2048) + cB);
            #pragma unroll
            for (int mi = 0; mi < 4; mi++)
                #pragma unroll
                for (int nj2 = 0; nj2 < 4; nj2++) {
                    mma16(acc[mi][2 * nj2],     a[mi], b[nj2][0], b[nj2][1]);
                    mma16(acc[mi][2 * nj2 + 1], a[mi], b[nj2][2], b[nj2][3]);
                }
        }
    }
    asm volatile("cp.async.wait_group 0;" ::: "memory");

    // ---- store my product tile to g_P ----
    const int qc   = lane & 3;
    const int rofs = lane >> 2;
    #pragma unroll
    for (int mi = 0; mi < 4; mi++) {
        const int row0 = M0 + wm * 64 + mi * 16 + rofs;
        #pragma unroll
        for (int nj = 0; nj < 8; nj++) {
            const int col = N0 + wn * 64 + nj * 8 + 2 * qc;
            *reinterpret_cast<float2*>(gP + (size_t)row0 * NC + col) =
                make_float2(acc[mi][nj][0], acc[mi][nj][1]);
            *reinterpret_cast<float2*>(gP + (size_t)(row0 + 8) * NC + col) =
                make_float2(acc[mi][nj][2], acc[mi][nj][3]);
        }
    }
    __threadfence();     // publish P stores before arrival increment
    __syncthreads();     // all threads' stores issued + fenced

    volatile unsigned* flag = reinterpret_cast<volatile unsigned*>(smem + FLAG_OFF);
    if (tid == 0) {
        unsigned r = atomicAdd(&g_cnt[tileid], 1u);
        unsigned last = (r == 2u);
        if (last) g_cnt[tileid] = 0u;    // self-reset for next graph replay
        __threadfence();
        *flag = last;
    }
    __syncthreads();
    if (*flag == 0u) return;             // not last: done

    // ================= last sibling: combine + blades + normalize =================
    // stash my product into dead pipeline smem: S[128][SROW]
    float* S = reinterpret_cast<float*>(smem);
    #pragma unroll
    for (int mi = 0; mi < 4; mi++) {
        const int rl = wm * 64 + mi * 16 + rofs;
        #pragma unroll
        for (int nj = 0; nj < 8; nj++) {
            const int cl = wn * 64 + nj * 8 + 2 * qc;
            *reinterpret_cast<float2*>(&S[rl * SROW + cl]) =
                make_float2(acc[mi][nj][0], acc[mi][nj][1]);
            *reinterpret_cast<float2*>(&S[(rl + 8) * SROW + cl]) =
                make_float2(acc[mi][nj][2], acc[mi][nj][3]);
        }
    }
    __syncthreads();

    const int za = (z + 1) % 3, zb = (z + 2) % 3;
    const float* Pa = g_P + (size_t)za * P_CHUNK;
    const float* Pb = g_P + (size_t)zb * P_CHUNK;

    #pragma unroll 1
    for (int e = 0; e < 8; e++) {
        const int cell = tid + e * 128;      // 0..1023
        const int t = cell >> 5;             // token within tile 0..31
        const int g = cell & 31;             // o-group 0..31
        float Mre[4][4], Mim[4][4];
        #pragma unroll
        for (int c = 0; c < 4; c++) {
            const size_t goff = (size_t)(M0 + 4 * t + c) * NC + N0 + 4 * g;
            float4 vo = *reinterpret_cast<const float4*>(&S[(4 * t + c) * SROW + 4 * g]);
            float4 va = *reinterpret_cast<const float4*>(Pa + goff);
            float4 vb = *reinterpret_cast<const float4*>(Pb + goff);
            float4 p1, p2, p3;
            if (z == 0)      { p1 = vo; p2 = va; p3 = vb; }
            else if (z == 1) { p1 = vb; p2 = vo; p3 = va; }
            else             { p1 = va; p2 = vb; p3 = vo; }
            Mre[0][c] = p1.x - p2.x; Mim[0][c] = p3.x - p1.x - p2.x;
            Mre[1][c] = p1.y - p2.y; Mim[1][c] = p3.y - p1.y - p2.y;
            Mre[2][c] = p1.z - p2.z; Mim[2][c] = p3.z - p1.z - p2.z;
            Mre[3][c] = p1.w - p2.w; Mim[3][c] = p3.w - p1.w - p2.w;
        }
        float v[32];
        blades(v, Mre, Mim, std::make_integer_sequence<int, 32>{});
        float ss = 1e-6f;
        #pragma unroll
        for (int k = 0; k < 32; k++) ss += v[k] * v[k];
        const float inv = rsqrtf(ss);

        const int n_global = (M0 >> 2) + t;
        const int o_global = (N0 >> 2) + g;
        float4* dst = reinterpret_cast<float4*>(out + ((size_t)n_global * 256 + o_global) * 32);
        #pragma unroll
        for (int q = 0; q < 8; q++)
            dst[q] = make_float4(v[4*q] * inv, v[4*q+1] * inv, v[4*q+2] * inv, v[4*q+3] * inv);
    }
}

// ================= host =================
extern "C" void kernel_launch(void* const* d_in, const int* in_sizes, int n_in,
                              void* d_out, int out_size) {
    const float* x = (const float*)d_in[0];   // [2048, 256, 32]
    const float* w = (const float*)d_in[1];   // [256, 256, 32]
    float* out = (float*)d_out;               // [2048, 256, 32]

    fwd_x<<<(NTOK * IFEAT) / 128, 128>>>(x);
    fwd_w<<<(OFEAT * IFEAT) / 128, 128>>>(w);

    cudaFuncSetAttribute(versor_mma, cudaFuncAttributeMaxDynamicSharedMemorySize, SMEM_TOTAL);
    dim3 grid(3 * (NC / BN), MDIM / BM);      // x: ntile*3 + z (siblings adjacent)
    versor_mma<<<grid, 128, SMEM_TOTAL>>>(out);
}